// round 9
// baseline (speedup 1.0000x reference)
#include <cuda_runtime.h>

// Reverse (suffix) cummax along axis 1 of [B=16, H=128, W=128, C=256] fp32.
//
// R8: persistent-CTA version of R7's burst-separated segmented scan.
// 296 blocks (2/SM, single wave) grid-stride over the 4096 (b,w,c4-half)
// slabs. Eliminates 4096 block teardowns (each waits for store drain) and
// ~13 wave transitions; in the loop the next slab's load burst issues
// immediately after the previous slab's stores issue (stores are
// fire-and-forget). segmax is double-buffered so one __syncthreads per slab
// suffices.
//
// Per slab (unchanged from R7):
//  - Thread owns an 8-element h-segment of one float4 column.
//  - Block = 512 thr = 16 segments (warps) x 32 c4-lanes.
//  - Phase 1: 8 independent coalesced 512B/warp streaming loads.
//  - Phase 2: in-register local suffix max; segment maxes via smem; fold in
//    carry = max over later segments.
//  - Phase 3: 8 coalesced 512B/warp streaming stores.
// Traffic stays exactly read-once / write-once (512 MB).

#define B_DIM 16
#define H_DIM 128
#define W_DIM 128
#define C_DIM 256

#define C4      (C_DIM / 4)     // 64 float4 per (b,h,w) row
#define STRIDE4 (W_DIM * C4)    // 8192 float4 between consecutive h

#define SEG_LEN  8                   // h elements per thread
#define NSEG     (H_DIM / SEG_LEN)   // 16 segments per column
#define LANES    32                  // c4 lanes per block-slab (half of C4)
#define THREADS  (NSEG * LANES)      // 512
#define NSLABS   (B_DIM * W_DIM * (C4 / LANES))  // 4096
#define BLOCKS   296                 // 2 per SM, single wave

__device__ __forceinline__ float4 f4max(float4 a, float4 b) {
    float4 r;
    r.x = fmaxf(a.x, b.x);
    r.y = fmaxf(a.y, b.y);
    r.z = fmaxf(a.z, b.z);
    r.w = fmaxf(a.w, b.w);
    return r;
}

__global__ void __launch_bounds__(THREADS, 2)
leftpool_rev_cummax_persist_kernel(const float4* __restrict__ in,
                                   float4* __restrict__ out) {
    __shared__ float4 segmax[2][NSEG * LANES];   // 2 x 8 KB, double-buffered

    const int seg  = threadIdx.x >> 5;        // 0..15 (warp id = segment)
    const int lane = threadIdx.x & 31;        // 0..31

    int buf = 0;
    for (int s = blockIdx.x; s < NSLABS; s += BLOCKS, buf ^= 1) {
        // slab s = (b*W + w) * 2 + half
        const int half = s & 1;
        const int bw   = s >> 1;
        const int b    = bw / W_DIM;
        const int w    = bw - b * W_DIM;
        const int c4   = half * LANES + lane;

        // float4 offset of (b, h = seg*SEG_LEN, w, c4)
        const int base = ((b * H_DIM + seg * SEG_LEN) * W_DIM + w) * C4 + c4;

        // ---- Phase 1: burst load (8 independent coalesced streaming loads)
        float4 v[SEG_LEN];
        #pragma unroll
        for (int i = 0; i < SEG_LEN; ++i)
            v[i] = __ldcs(&in[base + i * STRIDE4]);

        // ---- Phase 2a: local suffix max in registers
        #pragma unroll
        for (int i = SEG_LEN - 2; i >= 0; --i)
            v[i] = f4max(v[i], v[i + 1]);

        segmax[buf][seg * LANES + lane] = v[0];
        __syncthreads();

        // ---- Phase 2b: carry = max over all later segments (same column)
        float4 carry;
        carry.x = carry.y = carry.z = carry.w = __int_as_float(0xff800000);
        for (int t = seg + 1; t < NSEG; ++t)          // uniform per warp
            carry = f4max(carry, segmax[buf][t * LANES + lane]);

        #pragma unroll
        for (int i = 0; i < SEG_LEN; ++i)
            v[i] = f4max(v[i], carry);

        // ---- Phase 3: burst store (8 coalesced streaming stores, no drain
        //      wait: next slab's loads issue right behind these)
        #pragma unroll
        for (int i = 0; i < SEG_LEN; ++i)
            __stcs(&out[base + i * STRIDE4], v[i]);
    }
}

extern "C" void kernel_launch(void* const* d_in, const int* in_sizes, int n_in,
                              void* d_out, int out_size) {
    const float4* in  = (const float4*)d_in[0];
    float4*       out = (float4*)d_out;
    leftpool_rev_cummax_persist_kernel<<<BLOCKS, THREADS>>>(in, out);
}

// round 10
// speedup vs baseline: 1.1459x; 1.1459x over previous
#include <cuda_runtime.h>

// Reverse (suffix) cummax along axis 1 of [B=16, H=128, W=128, C=256] fp32.
//
// R9: R7's burst-separated segmented scan with FINER blocks: 256 threads =
// 16 segments x 16 c4-lanes, <=64 regs -> 4 co-resident blocks/SM (vs R7's
// 2). Same 32 warps/SM, but 4 independent sync domains: while one block is
// in its sync/carry/store phase, three others keep the DRAM read queue fed.
// (R8 showed coupling slabs into one sync domain costs ~4pp DRAM; R7 vs R5
// showed more domains at fixed warps is the axis that moves the number.)
//
// Per block-slab:
//  - Thread owns an 8-element h-segment of one float4 column.
//  - 16 lanes = 16 adjacent float4 (256B) in C; a warp covers 2 segments.
//  - Phase 1: 8 independent coalesced streaming loads (2x256B per warp-ld).
//  - Phase 2: in-register local suffix max; segment maxes via 4KB smem;
//    carry = max over later segments.
//  - Phase 3: 8 coalesced streaming stores.
// Traffic exactly read-once / write-once (512 MB).

#define B_DIM 16
#define H_DIM 128
#define W_DIM 128
#define C_DIM 256

#define C4      (C_DIM / 4)     // 64 float4 per (b,h,w) row
#define STRIDE4 (W_DIM * C4)    // 8192 float4 between consecutive h

#define SEG_LEN  8                   // h elements per thread
#define NSEG     (H_DIM / SEG_LEN)   // 16 segments per column
#define LANES    16                  // c4 lanes per block (quarter of C4)
#define THREADS  (NSEG * LANES)      // 256
#define BLOCKS   (B_DIM * W_DIM * (C4 / LANES))  // 8192

__device__ __forceinline__ float4 f4max(float4 a, float4 b) {
    float4 r;
    r.x = fmaxf(a.x, b.x);
    r.y = fmaxf(a.y, b.y);
    r.z = fmaxf(a.z, b.z);
    r.w = fmaxf(a.w, b.w);
    return r;
}

__global__ void __launch_bounds__(THREADS, 4)
leftpool_rev_cummax_q_kernel(const float4* __restrict__ in,
                             float4* __restrict__ out) {
    __shared__ float4 segmax[NSEG * LANES];   // 4 KB

    const int seg  = threadIdx.x / LANES;     // 0..15 (segment)
    const int lane = threadIdx.x % LANES;     // 0..15 (c4 within quarter)

    // blockIdx.x = (b * W + w) * 4 + quarter
    const int quarter = blockIdx.x & 3;
    const int bw      = blockIdx.x >> 2;      // b*W + w
    const int b = bw / W_DIM;
    const int w = bw - b * W_DIM;
    const int c4 = quarter * LANES + lane;

    // float4 offset of (b, h = seg*SEG_LEN, w, c4)
    const int base = ((b * H_DIM + seg * SEG_LEN) * W_DIM + w) * C4 + c4;

    // ---- Phase 1: burst load my segment (8 independent coalesced loads)
    float4 v[SEG_LEN];
    #pragma unroll
    for (int i = 0; i < SEG_LEN; ++i)
        v[i] = __ldcs(&in[base + i * STRIDE4]);

    // ---- Phase 2a: local (within-segment) suffix max, in registers
    #pragma unroll
    for (int i = SEG_LEN - 2; i >= 0; --i)
        v[i] = f4max(v[i], v[i + 1]);

    segmax[seg * LANES + lane] = v[0];
    __syncthreads();

    // ---- Phase 2b: carry = max over all later segments (same column)
    float4 carry;
    carry.x = carry.y = carry.z = carry.w = __int_as_float(0xff800000); // -inf
    for (int t = seg + 1; t < NSEG; ++t)
        carry = f4max(carry, segmax[t * LANES + lane]);

    #pragma unroll
    for (int i = 0; i < SEG_LEN; ++i)
        v[i] = f4max(v[i], carry);

    // ---- Phase 3: burst store (8 coalesced streaming stores)
    #pragma unroll
    for (int i = 0; i < SEG_LEN; ++i)
        __stcs(&out[base + i * STRIDE4], v[i]);
}

extern "C" void kernel_launch(void* const* d_in, const int* in_sizes, int n_in,
                              void* d_out, int out_size) {
    const float4* in  = (const float4*)d_in[0];
    float4*       out = (float4*)d_out;
    leftpool_rev_cummax_q_kernel<<<BLOCKS, THREADS>>>(in, out);
}